// round 1
// baseline (speedup 1.0000x reference)
#include <cuda_runtime.h>
#include <cuda_bf16.h>
#include <cstdint>

// Problem constants
#define BQ   4
#define TQ   2048
#define DQ   1024
#define HQ   16
#define DKQ  64
#define DVQ  64
#define ROWS (BQ*TQ)   // 8192

// ---------------- scratch (static device memory; no allocation) ----------------
__device__ float g_xn  [ROWS*DQ];
__device__ float g_qpre[ROWS*DQ];
__device__ float g_kpre[ROWS*DQ];
__device__ float g_vpre[ROWS*DQ];
__device__ float g_gpre[ROWS*DQ];
__device__ float g_qn  [ROWS*DQ];
__device__ float g_kn  [ROWS*DQ];
__device__ float g_vn  [ROWS*DQ];
__device__ float g_beta [ROWS*HQ];
__device__ float g_decay[ROWS*HQ];
__device__ float g_osc [ROWS*DQ];
__device__ float g_gated[ROWS*DQ];

__device__ __forceinline__ float siluf(float x){ return x/(1.0f+expf(-x)); }

// ---------------- RMSNorm over D=1024 ----------------
__global__ __launch_bounds__(256) void rmsnorm_kernel(const float* __restrict__ x,
                                                      const float* __restrict__ w)
{
    int row = blockIdx.x;
    const float* xr = x + (size_t)row*DQ;
    float* o = g_xn + (size_t)row*DQ;
    int tid = threadIdx.x; // 256 threads, 4 elems each
    float4 v = *(const float4*)(xr + tid*4);
    float ss = v.x*v.x+v.y*v.y+v.z*v.z+v.w*v.w;
    #pragma unroll
    for (int m=16;m>0;m>>=1) ss += __shfl_xor_sync(0xffffffffu, ss, m);
    __shared__ float sred[8];
    if ((tid&31)==0) sred[tid>>5]=ss;
    __syncthreads();
    if (tid<8){
        float t = sred[tid];
        #pragma unroll
        for (int m=4;m>0;m>>=1) t += __shfl_xor_sync(0xffu, t, m);
        if (tid==0) sred[0]=t;
    }
    __syncthreads();
    float denom = rsqrtf(sred[0]*(1.0f/DQ) + 1e-5f);
    float4 wv = *(const float4*)(w + tid*4);
    float4 ov;
    ov.x = v.x*denom*wv.x; ov.y = v.y*denom*wv.y;
    ov.z = v.z*denom*wv.z; ov.w = v.w*denom*wv.w;
    *(float4*)(o + tid*4) = ov;
}

// ---------------- tf32 tensor-core GEMM: C[M,N] = A[M,K] @ W[K,N] (+Res) ----------------
#define GBM 128
#define GBN 128
#define GBK 16

__global__ __launch_bounds__(256) void gemm_tf32(const float* __restrict__ A,
                                                 const float* __restrict__ W,
                                                 const float* __restrict__ Res,
                                                 float* __restrict__ C,
                                                 int M, int N, int K, int residual)
{
    __shared__ float As[2][GBK][GBM+8];
    __shared__ float Bs[2][GBK][GBN+8];
    const int tid = threadIdx.x;
    const int bm = blockIdx.y*GBM, bn = blockIdx.x*GBN;
    const int wid = tid>>5, lane = tid&31;
    const int wm = (wid>>2)*64, wn = (wid&3)*32;
    const int r = lane>>2, c4 = lane&3;

    float acc[4][4][4];
    #pragma unroll
    for (int i=0;i<4;i++)
        #pragma unroll
        for (int j=0;j<4;j++)
            #pragma unroll
            for (int k=0;k<4;k++) acc[i][j][k]=0.f;

    const int am = tid>>1, akb = (tid&1)*8;
    const float* aptr = A + (size_t)(bm+am)*K + akb;
    const int nk = K/GBK;

    for (int kt=0; kt<=nk; kt++){
        if (kt<nk){
            int buf = kt&1;
            float4 a0 = *(const float4*)(aptr + (size_t)kt*GBK);
            float4 a1 = *(const float4*)(aptr + (size_t)kt*GBK + 4);
            As[buf][akb+0][am]=a0.x; As[buf][akb+1][am]=a0.y;
            As[buf][akb+2][am]=a0.z; As[buf][akb+3][am]=a0.w;
            As[buf][akb+4][am]=a1.x; As[buf][akb+5][am]=a1.y;
            As[buf][akb+6][am]=a1.z; As[buf][akb+7][am]=a1.w;
            #pragma unroll
            for (int rr=0; rr<2; rr++){
                int i = tid + rr*256;
                int kk = i>>5, n4 = (i&31)*4;
                *(float4*)&Bs[buf][kk][n4] =
                    *(const float4*)(W + (size_t)(kt*GBK+kk)*N + bn + n4);
            }
        }
        if (kt>0){
            int buf = (kt-1)&1;
            #pragma unroll
            for (int ks=0; ks<GBK; ks+=8){
                uint32_t af[4][4], bf[4][2];
                #pragma unroll
                for (int mt=0;mt<4;mt++){
                    int mr = wm + mt*16 + r;
                    af[mt][0] = __float_as_uint(As[buf][ks+c4  ][mr]);
                    af[mt][1] = __float_as_uint(As[buf][ks+c4  ][mr+8]);
                    af[mt][2] = __float_as_uint(As[buf][ks+c4+4][mr]);
                    af[mt][3] = __float_as_uint(As[buf][ks+c4+4][mr+8]);
                }
                #pragma unroll
                for (int nt=0;nt<4;nt++){
                    int nc = wn + nt*8 + r;
                    bf[nt][0] = __float_as_uint(Bs[buf][ks+c4  ][nc]);
                    bf[nt][1] = __float_as_uint(Bs[buf][ks+c4+4][nc]);
                }
                #pragma unroll
                for (int mt=0;mt<4;mt++)
                    #pragma unroll
                    for (int nt=0;nt<4;nt++)
                        asm volatile(
                          "mma.sync.aligned.m16n8k8.row.col.f32.tf32.tf32.f32 "
                          "{%0,%1,%2,%3},{%4,%5,%6,%7},{%8,%9},{%0,%1,%2,%3};"
                          : "+f"(acc[mt][nt][0]),"+f"(acc[mt][nt][1]),
                            "+f"(acc[mt][nt][2]),"+f"(acc[mt][nt][3])
                          : "r"(af[mt][0]),"r"(af[mt][1]),"r"(af[mt][2]),"r"(af[mt][3]),
                            "r"(bf[nt][0]),"r"(bf[nt][1]));
            }
        }
        __syncthreads();
    }

    #pragma unroll
    for (int mt=0;mt<4;mt++){
        #pragma unroll
        for (int nt=0;nt<4;nt++){
            int m0 = bm + wm + mt*16 + r;
            int n0 = bn + wn + nt*8 + c4*2;
            size_t i0 = (size_t)m0*N + n0;
            size_t i1 = (size_t)(m0+8)*N + n0;
            float2 v0 = make_float2(acc[mt][nt][0], acc[mt][nt][1]);
            float2 v1 = make_float2(acc[mt][nt][2], acc[mt][nt][3]);
            if (residual){
                float2 r0 = *(const float2*)(Res + i0);
                float2 r1 = *(const float2*)(Res + i1);
                v0.x+=r0.x; v0.y+=r0.y; v1.x+=r1.x; v1.y+=r1.y;
            }
            *(float2*)(C+i0)=v0;
            *(float2*)(C+i1)=v1;
        }
    }
}

// ---------------- depthwise causal conv (K=4) + SiLU (+ optional L2 norm per head) ----------------
// mode: 0 = none (v), 1 = l2 normalize (k), 2 = l2 normalize * DK^-0.5 (q)
__device__ __forceinline__ void conv_one(const float* __restrict__ pre,
                                         const float* __restrict__ w,
                                         float* __restrict__ out,
                                         int bt, int t, int tid, int mode)
{
    int c0 = tid*4;
    const float* base = pre + (size_t)bt*DQ + c0;
    float4 w0 = *(const float4*)(w + (size_t)(c0+0)*4);
    float4 w1 = *(const float4*)(w + (size_t)(c0+1)*4);
    float4 w2 = *(const float4*)(w + (size_t)(c0+2)*4);
    float4 w3 = *(const float4*)(w + (size_t)(c0+3)*4);
    float a0=0.f,a1=0.f,a2=0.f,a3=0.f;
    #pragma unroll
    for (int j=0;j<4;j++){
        if (t-j >= 0){
            float4 xv = *(const float4*)(base - (size_t)j*DQ);
            a0 += xv.x*((const float*)&w0)[j];
            a1 += xv.y*((const float*)&w1)[j];
            a2 += xv.z*((const float*)&w2)[j];
            a3 += xv.w*((const float*)&w3)[j];
        }
    }
    a0 = siluf(a0); a1 = siluf(a1); a2 = siluf(a2); a3 = siluf(a3);
    if (mode){
        float ss = a0*a0+a1*a1+a2*a2+a3*a3;
        ss += __shfl_xor_sync(0xffffffffu, ss, 1);
        ss += __shfl_xor_sync(0xffffffffu, ss, 2);
        ss += __shfl_xor_sync(0xffffffffu, ss, 4);
        ss += __shfl_xor_sync(0xffffffffu, ss, 8);
        float scale = (mode==2) ? 0.125f : 1.0f;      // DK^-0.5 = 1/8
        float inv = scale / fmaxf(sqrtf(ss), 1e-12f);
        a0*=inv; a1*=inv; a2*=inv; a3*=inv;
    }
    float4 ov; ov.x=a0; ov.y=a1; ov.z=a2; ov.w=a3;
    *(float4*)(out + (size_t)bt*DQ + c0) = ov;
}

__global__ __launch_bounds__(256) void conv_kernel(const float* __restrict__ qw,
                                                   const float* __restrict__ kw,
                                                   const float* __restrict__ vw)
{
    int bt = blockIdx.x;
    int t  = bt & (TQ-1);
    int tid = threadIdx.x;
    conv_one(g_qpre, qw, g_qn, bt, t, tid, 2);
    conv_one(g_kpre, kw, g_kn, bt, t, tid, 1);
    conv_one(g_vpre, vw, g_vn, bt, t, tid, 0);
}

// ---------------- beta = sigmoid(xn@b_proj) ; decay = exp(-exp(A_log)*softplus(xn@a_proj+dt_bias)) ----------------
__global__ __launch_bounds__(256) void betadecay_kernel(const float* __restrict__ bp,
                                                        const float* __restrict__ ap,
                                                        const float* __restrict__ Alog,
                                                        const float* __restrict__ dtb)
{
    int row = blockIdx.x;
    __shared__ float xr[DQ];
    int tid = threadIdx.x;
    *(float4*)&xr[tid*4] = *(const float4*)(g_xn + (size_t)row*DQ + tid*4);
    __syncthreads();
    int w = tid>>5, lane = tid&31;
    #pragma unroll
    for (int oi=0; oi<4; oi++){
        int outi = w*4+oi;                 // 0..31 : 0-15 beta, 16-31 dt
        const float* P = (outi<HQ) ? bp : ap;
        int h = outi & (HQ-1);
        float s = 0.f;
        #pragma unroll 8
        for (int d=lane; d<DQ; d+=32) s += xr[d]*P[d*HQ + h];
        #pragma unroll
        for (int m=16;m>0;m>>=1) s += __shfl_xor_sync(0xffffffffu, s, m);
        if (lane==0){
            if (outi<HQ){
                g_beta[(size_t)row*HQ+h] = 1.0f/(1.0f+expf(-s));
            } else {
                float xdt = s + dtb[h];
                float sp = (xdt>20.f) ? xdt : log1pf(expf(xdt));
                g_decay[(size_t)row*HQ+h] = expf(-expf(Alog[h])*sp);
            }
        }
    }
}

// ---------------- gated delta-rule scan ----------------
// one CTA per (b,h,v-half): 128 CTAs, 256 threads = 32 columns x 8 DK-splits
#define SCH 16
__global__ __launch_bounds__(256) void scan_kernel()
{
    const int half = blockIdx.x & 1;
    const int bh   = blockIdx.x >> 1;
    const int b = bh >> 4, h = bh & 15;
    const int tid = threadIdx.x;
    const int el = tid >> 3;       // DV column within half: 0..31
    const int s  = tid & 7;        // DK split: 0..7
    const int d0 = s*8;

    __shared__ float qs[2][SCH*64];
    __shared__ float ks[2][SCH*64];
    __shared__ float vs[2][SCH*32];
    __shared__ float bs[2][SCH];
    __shared__ float ds[2][SCH];

    float S[8];
    #pragma unroll
    for (int i=0;i<8;i++) S[i]=0.f;

    const size_t hb = ((size_t)b*TQ*HQ + h)*64;
    const float* qg = g_qn + hb;
    const float* kg = g_kn + hb;
    const float* vg = g_vn + hb + half*32;
    const float* bg = g_beta  + (size_t)b*TQ*HQ + h;
    const float* dg = g_decay + (size_t)b*TQ*HQ + h;
    float* og = g_osc + hb + half*32 + el;
    const size_t tstr = (size_t)HQ*64;   // 1024 floats per t

    const int tt  = tid>>4, d4  = (tid&15)*4;   // q/k chunk element
    const int tv  = tid>>3, dv4 = (tid&7)*4;    // v chunk element

    // chunk 0
    {
        *(float4*)&qs[0][tt*64+d4] = *(const float4*)(qg + (size_t)tt*tstr + d4);
        *(float4*)&ks[0][tt*64+d4] = *(const float4*)(kg + (size_t)tt*tstr + d4);
        if (tid<128)      *(float4*)&vs[0][tv*32+dv4] = *(const float4*)(vg + (size_t)tv*tstr + dv4);
        else if (tid<144) bs[0][tid-128] = bg[(size_t)(tid-128)*HQ];
        else if (tid<160) ds[0][tid-144] = dg[(size_t)(tid-144)*HQ];
    }
    __syncthreads();

    const int NC = TQ/SCH;   // 128 chunks
    for (int c=0; c<NC; c++){
        const int cur = c&1, nxt = cur^1;
        // register prefetch for next chunk (overlaps with compute)
        float4 pq, pk, pv; float pb=0.f, pd=0.f;
        const bool has = (c+1<NC);
        const int t0n = (c+1)*SCH;
        if (has){
            pq = *(const float4*)(qg + (size_t)(t0n+tt)*tstr + d4);
            pk = *(const float4*)(kg + (size_t)(t0n+tt)*tstr + d4);
            if (tid<128)      pv = *(const float4*)(vg + (size_t)(t0n+tv)*tstr + dv4);
            else if (tid<144) pb = bg[(size_t)(t0n+tid-128)*HQ];
            else if (tid<160) pd = dg[(size_t)(t0n+tid-144)*HQ];
        }
        const int t0 = c*SCH;
        #pragma unroll 4
        for (int j=0;j<SCH;j++){
            float kr[8], qr[8];
            *(float4*)&kr[0] = *(const float4*)&ks[cur][j*64+d0];
            *(float4*)&kr[4] = *(const float4*)&ks[cur][j*64+d0+4];
            float dcy = ds[cur][j];
            float bet = bs[cur][j];
            float vv  = vs[cur][j*32+el];
            float p0=0.f,p1=0.f;
            #pragma unroll
            for (int i=0;i<8;i+=2){
                S[i]   *= dcy; p0 += kr[i]  *S[i];
                S[i+1] *= dcy; p1 += kr[i+1]*S[i+1];
            }
            float pred = p0+p1;
            pred += __shfl_xor_sync(0xffffffffu, pred, 1);
            pred += __shfl_xor_sync(0xffffffffu, pred, 2);
            pred += __shfl_xor_sync(0xffffffffu, pred, 4);
            float be = bet*(vv - pred);
            *(float4*)&qr[0] = *(const float4*)&qs[cur][j*64+d0];
            *(float4*)&qr[4] = *(const float4*)&qs[cur][j*64+d0+4];
            float o0=0.f,o1=0.f;
            #pragma unroll
            for (int i=0;i<8;i+=2){
                S[i]   = fmaf(kr[i],  be,S[i]);   o0 += qr[i]  *S[i];
                S[i+1] = fmaf(kr[i+1],be,S[i+1]); o1 += qr[i+1]*S[i+1];
            }
            float oo = o0+o1;
            oo += __shfl_xor_sync(0xffffffffu, oo, 1);
            oo += __shfl_xor_sync(0xffffffffu, oo, 2);
            oo += __shfl_xor_sync(0xffffffffu, oo, 4);
            if (s==0) og[(size_t)(t0+j)*tstr] = oo;
        }
        __syncthreads();
        if (has){
            *(float4*)&qs[nxt][tt*64+d4] = pq;
            *(float4*)&ks[nxt][tt*64+d4] = pk;
            if (tid<128)      *(float4*)&vs[nxt][tv*32+dv4] = pv;
            else if (tid<144) bs[nxt][tid-128] = pb;
            else if (tid<160) ds[nxt][tid-144] = pd;
        }
        __syncthreads();
    }
}

// ---------------- output gate: rmsnorm(o, 64)*o_norm_scale * silu(gate) ----------------
__global__ __launch_bounds__(256) void gate_kernel(const float* __restrict__ onorm)
{
    int row = blockIdx.x;
    int tid = threadIdx.x;
    int c0 = tid*4;
    size_t off = (size_t)row*DQ + c0;
    float4 o = *(const float4*)(g_osc + off);
    float ss = o.x*o.x+o.y*o.y+o.z*o.z+o.w*o.w;
    ss += __shfl_xor_sync(0xffffffffu, ss, 1);
    ss += __shfl_xor_sync(0xffffffffu, ss, 2);
    ss += __shfl_xor_sync(0xffffffffu, ss, 4);
    ss += __shfl_xor_sync(0xffffffffu, ss, 8);
    float denom = rsqrtf(ss*(1.0f/64.f) + 1e-5f);
    int dv = c0 & 63;
    float4 w = *(const float4*)(onorm + dv);
    float4 g = *(const float4*)(g_gpre + off);
    float4 res;
    res.x = o.x*denom*w.x*siluf(g.x);
    res.y = o.y*denom*w.y*siluf(g.y);
    res.z = o.z*denom*w.z*siluf(g.z);
    res.w = o.w*denom*w.w*siluf(g.w);
    *(float4*)(g_gated + off) = res;
}

// ---------------- launch ----------------
extern "C" void kernel_launch(void* const* d_in, const int* in_sizes, int n_in,
                              void* d_out, int out_size)
{
    const float* x      = (const float*)d_in[0];
    const float* nscale = (const float*)d_in[1];
    const float* wq     = (const float*)d_in[2];
    const float* wk     = (const float*)d_in[3];
    const float* wv     = (const float*)d_in[4];
    const float* qcw    = (const float*)d_in[5];
    const float* kcw    = (const float*)d_in[6];
    const float* vcw    = (const float*)d_in[7];
    const float* aproj  = (const float*)d_in[8];
    const float* Alog   = (const float*)d_in[9];
    const float* dtb    = (const float*)d_in[10];
    const float* bproj  = (const float*)d_in[11];
    const float* gproj  = (const float*)d_in[12];
    const float* onorm  = (const float*)d_in[13];
    const float* wo     = (const float*)d_in[14];
    float* out = (float*)d_out;

    void *pxn, *pqpre, *pkpre, *pvpre, *pgpre, *pgated;
    cudaGetSymbolAddress(&pxn,   g_xn);
    cudaGetSymbolAddress(&pqpre, g_qpre);
    cudaGetSymbolAddress(&pkpre, g_kpre);
    cudaGetSymbolAddress(&pvpre, g_vpre);
    cudaGetSymbolAddress(&pgpre, g_gpre);
    cudaGetSymbolAddress(&pgated,g_gated);

    rmsnorm_kernel<<<ROWS, 256>>>(x, nscale);

    dim3 ggrid(DQ/GBN, ROWS/GBM);   // (8, 64)
    gemm_tf32<<<ggrid, 256>>>((const float*)pxn, wq,    nullptr, (float*)pqpre, ROWS, DQ, DQ, 0);
    gemm_tf32<<<ggrid, 256>>>((const float*)pxn, wk,    nullptr, (float*)pkpre, ROWS, DQ, DQ, 0);
    gemm_tf32<<<ggrid, 256>>>((const float*)pxn, wv,    nullptr, (float*)pvpre, ROWS, DQ, DQ, 0);
    gemm_tf32<<<ggrid, 256>>>((const float*)pxn, gproj, nullptr, (float*)pgpre, ROWS, DQ, DQ, 0);

    betadecay_kernel<<<ROWS, 256>>>(bproj, aproj, Alog, dtb);
    conv_kernel<<<ROWS, 256>>>(qcw, kcw, vcw);

    scan_kernel<<<BQ*HQ*2, 256>>>();

    gate_kernel<<<ROWS, 256>>>(onorm);

    gemm_tf32<<<ggrid, 256>>>((const float*)pgated, wo, x, out, ROWS, DQ, DQ, 1);
}

// round 5
// speedup vs baseline: 1.9797x; 1.9797x over previous
#include <cuda_runtime.h>
#include <cuda_fp16.h>
#include <cstdint>

// Problem constants
#define BQ   4
#define TQ   2048
#define DQ   1024
#define HQ   16
#define ROWS (BQ*TQ)   // 8192
#define NW   4224      // fused projection width: q|k|v|g|bp|ap|pad

// ---------------- scratch (static device memory) ----------------
__device__ float g_xn   [ROWS*DQ];
__device__ float g_pre  [(size_t)ROWS*NW];
__device__ float g_qn   [ROWS*DQ];
__device__ float g_kn   [ROWS*DQ];
__device__ float g_vn   [ROWS*DQ];
__device__ float g_beta [ROWS*HQ];
__device__ float g_decay[ROWS*HQ];
__device__ float g_qk   [ROWS*HQ];
__device__ float g_osc  [ROWS*DQ];
__device__ float g_gated[ROWS*DQ];
__device__ float g_wbig [(size_t)DQ*NW];

__device__ __forceinline__ float siluf(float x){ return x/(1.0f+expf(-x)); }
__device__ __forceinline__ uint32_t packh2(float a, float b){
    __half2 h = __floats2half2_rn(a, b);
    return *reinterpret_cast<uint32_t*>(&h);
}

// ---------------- RMSNorm over D=1024 ----------------
__global__ __launch_bounds__(256) void rmsnorm_kernel(const float* __restrict__ x,
                                                      const float* __restrict__ w)
{
    int row = blockIdx.x;
    const float* xr = x + (size_t)row*DQ;
    float* o = g_xn + (size_t)row*DQ;
    int tid = threadIdx.x;
    float4 v = *(const float4*)(xr + tid*4);
    float ss = v.x*v.x+v.y*v.y+v.z*v.z+v.w*v.w;
    #pragma unroll
    for (int m=16;m>0;m>>=1) ss += __shfl_xor_sync(0xffffffffu, ss, m);
    __shared__ float sred[8];
    if ((tid&31)==0) sred[tid>>5]=ss;
    __syncthreads();
    if (tid<8){
        float t = sred[tid];
        #pragma unroll
        for (int m=4;m>0;m>>=1) t += __shfl_xor_sync(0xffu, t, m);
        if (tid==0) sred[0]=t;
    }
    __syncthreads();
    float denom = rsqrtf(sred[0]*(1.0f/DQ) + 1e-5f);
    float4 wv = *(const float4*)(w + tid*4);
    float4 ov;
    ov.x = v.x*denom*wv.x; ov.y = v.y*denom*wv.y;
    ov.z = v.z*denom*wv.z; ov.w = v.w*denom*wv.w;
    *(float4*)(o + tid*4) = ov;
}

// ---------------- weight concat: Wbig[K=1024][4224] ----------------
__global__ __launch_bounds__(256) void concat_w(const float* __restrict__ wq,
                                                const float* __restrict__ wk,
                                                const float* __restrict__ wv,
                                                const float* __restrict__ gp,
                                                const float* __restrict__ bp,
                                                const float* __restrict__ ap)
{
    int k = blockIdx.x;     // 0..1023
    float* o = g_wbig + (size_t)k*NW;
    for (int c4 = threadIdx.x; c4 < NW/4; c4 += 256){
        int c = c4*4;
        float4 v;
        if      (c < 1024) v = *(const float4*)(wq + (size_t)k*DQ + c);
        else if (c < 2048) v = *(const float4*)(wk + (size_t)k*DQ + c - 1024);
        else if (c < 3072) v = *(const float4*)(wv + (size_t)k*DQ + c - 2048);
        else if (c < 4096) v = *(const float4*)(gp + (size_t)k*DQ + c - 3072);
        else if (c < 4112) v = *(const float4*)(bp + (size_t)k*HQ + c - 4096);
        else if (c < 4128) v = *(const float4*)(ap + (size_t)k*HQ + c - 4112);
        else               v = make_float4(0.f,0.f,0.f,0.f);
        *(float4*)(o + c) = v;
    }
}

// ---------------- fp16 tensor-core GEMM: C[M,Nw] = A[M,1024] @ W[1024,Nw] (+Res) ----------------
// CTA tile 128x128, KT=32, single smem buffer + register prefetch.
#define KTG 32
#define NKT (DQ/KTG)   // 32

__global__ __launch_bounds__(256) void gemm_fp16(const float* __restrict__ A,
                                                 const float* __restrict__ W,
                                                 const float* __restrict__ Res,
                                                 float* __restrict__ C,
                                                 int Nw, int residual)
{
    __shared__ uint32_t As2[16][136];   // [k2][m]  half2 along K
    __shared__ uint32_t Bs2[16][136];   // [k2][n]

    const int tid = threadIdx.x;
    const int wid = tid>>5, lane = tid&31;
    const int bm = blockIdx.y*128, bn = blockIdx.x*128;
    const int wm = (wid>>2)*64, wn = (wid&3)*32;
    const int r = lane>>2, c4 = lane&3;

    float acc[4][4][4];
    #pragma unroll
    for (int i=0;i<4;i++)
        #pragma unroll
        for (int j=0;j<4;j++)
            #pragma unroll
            for (int k=0;k<4;k++) acc[i][j][k]=0.f;

    // A loader: 8 threads/row, 1 float4 each, 4 row-passes
    const int am  = tid>>3;          // 0..31
    const int ak4 = (tid&7)*4;       // 0,4,..,28
    const int ak2 = (tid&7)*2;       // k2 of the pair
    const float* aptr = A + (size_t)(bm+am)*DQ + ak4;
    // B loader: 32 lanes cover a 128-wide row, 8 warps cover k2 0..7 (+8 second pass)
    const int bk2 = tid>>5;          // 0..7
    const int bn4 = lane*4;
    const float* bptr = W + (size_t)(2*bk2)*Nw + bn + bn4;

    float4 fa[4], fb[4];

    auto LDG_TILE = [&](int k0){
        #pragma unroll
        for (int i=0;i<4;i++)
            fa[i] = *(const float4*)(aptr + (size_t)(32*i)*DQ + k0);
        fb[0] = *(const float4*)(bptr + (size_t)(k0   )*Nw);
        fb[1] = *(const float4*)(bptr + (size_t)(k0+1 )*Nw);
        fb[2] = *(const float4*)(bptr + (size_t)(k0+16)*Nw);
        fb[3] = *(const float4*)(bptr + (size_t)(k0+17)*Nw);
    };
    auto STS_TILE = [&](){
        #pragma unroll
        for (int i=0;i<4;i++){
            As2[ak2  ][am+32*i] = packh2(fa[i].x, fa[i].y);
            As2[ak2+1][am+32*i] = packh2(fa[i].z, fa[i].w);
        }
        #pragma unroll
        for (int p=0;p<2;p++){
            const float4& e = fb[2*p];
            const float4& o = fb[2*p+1];
            uint4 w4;
            w4.x = packh2(e.x, o.x); w4.y = packh2(e.y, o.y);
            w4.z = packh2(e.z, o.z); w4.w = packh2(e.w, o.w);
            *(uint4*)&Bs2[bk2+8*p][bn4] = w4;
        }
    };

    LDG_TILE(0);
    STS_TILE();
    __syncthreads();

    for (int it=0; it<NKT; it++){
        if (it+1 < NKT) LDG_TILE((it+1)*KTG);

        #pragma unroll
        for (int s=0;s<2;s++){
            const int ks2 = s*8;
            uint32_t af[4][4], bf[4][2];
            #pragma unroll
            for (int mt=0;mt<4;mt++){
                int m = wm + mt*16 + r;
                af[mt][0] = As2[ks2+c4  ][m];
                af[mt][1] = As2[ks2+c4  ][m+8];
                af[mt][2] = As2[ks2+c4+4][m];
                af[mt][3] = As2[ks2+c4+4][m+8];
            }
            #pragma unroll
            for (int nt=0;nt<4;nt++){
                int n = wn + nt*8 + r;
                bf[nt][0] = Bs2[ks2+c4  ][n];
                bf[nt][1] = Bs2[ks2+c4+4][n];
            }
            #pragma unroll
            for (int mt=0;mt<4;mt++)
                #pragma unroll
                for (int nt=0;nt<4;nt++)
                    asm volatile(
                      "mma.sync.aligned.m16n8k16.row.col.f32.f16.f16.f32 "
                      "{%0,%1,%2,%3},{%4,%5,%6,%7},{%8,%9},{%0,%1,%2,%3};"
                      : "+f"(acc[mt][nt][0]),"+f"(acc[mt][nt][1]),
                        "+f"(acc[mt][nt][2]),"+f"(acc[mt][nt][3])
                      : "r"(af[mt][0]),"r"(af[mt][1]),"r"(af[mt][2]),"r"(af[mt][3]),
                        "r"(bf[nt][0]),"r"(bf[nt][1]));
        }
        __syncthreads();
        if (it+1 < NKT){
            STS_TILE();
            __syncthreads();
        }
    }

    #pragma unroll
    for (int mt=0;mt<4;mt++){
        #pragma unroll
        for (int nt=0;nt<4;nt++){
            int m0 = bm + wm + mt*16 + r;
            int n0 = bn + wn + nt*8 + c4*2;
            size_t i0 = (size_t)m0*Nw + n0;
            size_t i1 = (size_t)(m0+8)*Nw + n0;
            float2 v0 = make_float2(acc[mt][nt][0], acc[mt][nt][1]);
            float2 v1 = make_float2(acc[mt][nt][2], acc[mt][nt][3]);
            if (residual){
                float2 r0 = *(const float2*)(Res + i0);
                float2 r1 = *(const float2*)(Res + i1);
                v0.x+=r0.x; v0.y+=r0.y; v1.x+=r1.x; v1.y+=r1.y;
            }
            *(float2*)(C+i0)=v0;
            *(float2*)(C+i1)=v1;
        }
    }
}

// ---------------- depthwise causal conv (K=4) + SiLU + L2 norm + qk dot ----------------
__device__ __forceinline__ void conv4(const float* __restrict__ base, // g_pre row ptr at channel c0
                                      const float* __restrict__ w, int c0, int t,
                                      float& a0, float& a1, float& a2, float& a3)
{
    float4 w0 = *(const float4*)(w + (size_t)(c0+0)*4);
    float4 w1 = *(const float4*)(w + (size_t)(c0+1)*4);
    float4 w2 = *(const float4*)(w + (size_t)(c0+2)*4);
    float4 w3 = *(const float4*)(w + (size_t)(c0+3)*4);
    a0=0.f; a1=0.f; a2=0.f; a3=0.f;
    #pragma unroll
    for (int j=0;j<4;j++){
        if (t-j >= 0){
            float4 xv = *(const float4*)(base - (size_t)j*NW);
            a0 += xv.x*((const float*)&w0)[j];
            a1 += xv.y*((const float*)&w1)[j];
            a2 += xv.z*((const float*)&w2)[j];
            a3 += xv.w*((const float*)&w3)[j];
        }
    }
    a0 = siluf(a0); a1 = siluf(a1); a2 = siluf(a2); a3 = siluf(a3);
}

__device__ __forceinline__ void l2n4(float& a0, float& a1, float& a2, float& a3, float scale)
{
    float ss = a0*a0+a1*a1+a2*a2+a3*a3;
    ss += __shfl_xor_sync(0xffffffffu, ss, 1);
    ss += __shfl_xor_sync(0xffffffffu, ss, 2);
    ss += __shfl_xor_sync(0xffffffffu, ss, 4);
    ss += __shfl_xor_sync(0xffffffffu, ss, 8);
    float inv = scale / fmaxf(sqrtf(ss), 1e-12f);
    a0*=inv; a1*=inv; a2*=inv; a3*=inv;
}

__global__ __launch_bounds__(256) void conv_kernel(const float* __restrict__ qw,
                                                   const float* __restrict__ kw,
                                                   const float* __restrict__ vw)
{
    int bt = blockIdx.x;
    int t  = bt & (TQ-1);
    int tid = threadIdx.x;
    int c0 = tid*4;
    const float* rowbase = g_pre + (size_t)bt*NW + c0;
    size_t off = (size_t)bt*DQ + c0;

    float q0,q1,q2,q3, k0,k1,k2,k3, v0,v1,v2,v3;
    conv4(rowbase,          qw, c0, t, q0,q1,q2,q3);
    l2n4(q0,q1,q2,q3, 0.125f);
    *(float4*)(g_qn + off) = make_float4(q0,q1,q2,q3);

    conv4(rowbase + 1024,   kw, c0, t, k0,k1,k2,k3);
    l2n4(k0,k1,k2,k3, 1.0f);
    *(float4*)(g_kn + off) = make_float4(k0,k1,k2,k3);

    float qk = q0*k0 + q1*k1 + q2*k2 + q3*k3;
    qk += __shfl_xor_sync(0xffffffffu, qk, 1);
    qk += __shfl_xor_sync(0xffffffffu, qk, 2);
    qk += __shfl_xor_sync(0xffffffffu, qk, 4);
    qk += __shfl_xor_sync(0xffffffffu, qk, 8);
    if ((tid & 15) == 0) g_qk[(size_t)bt*HQ + (tid>>4)] = qk;

    conv4(rowbase + 2048,   vw, c0, t, v0,v1,v2,v3);
    *(float4*)(g_vn + off) = make_float4(v0,v1,v2,v3);
}

// ---------------- beta / decay from fused GEMM columns ----------------
__global__ __launch_bounds__(256) void betadecay_kernel(const float* __restrict__ Alog,
                                                        const float* __restrict__ dtb)
{
    int i = blockIdx.x*256 + threadIdx.x;   // ROWS*32
    int row = i >> 5, c = i & 31;
    float s = g_pre[(size_t)row*NW + 4096 + c];
    if (c < HQ){
        g_beta[(size_t)row*HQ + c] = 1.0f/(1.0f+expf(-s));
    } else {
        int h = c - HQ;
        float xdt = s + dtb[h];
        float sp = (xdt>20.f) ? xdt : log1pf(expf(xdt));
        g_decay[(size_t)row*HQ + h] = expf(-expf(Alog[h])*sp);
    }
}

// ---------------- gated delta-rule scan (shortened critical path) ----------------
#define SCH 16
__global__ __launch_bounds__(256) void scan_kernel()
{
    const int half = blockIdx.x & 1;
    const int bh   = blockIdx.x >> 1;
    const int b = bh >> 4, h = bh & 15;
    const int tid = threadIdx.x;
    const int el = tid >> 3;       // DV column within half: 0..31
    const int s  = tid & 7;        // DK split: 0..7
    const int d0 = s*8;

    __shared__ float qs[2][SCH*64];
    __shared__ float ks[2][SCH*64];
    __shared__ float vs[2][SCH*32];
    __shared__ float bs[2][SCH];
    __shared__ float ds[2][SCH];
    __shared__ float qks[2][SCH];

    float S[8];
    #pragma unroll
    for (int i=0;i<8;i++) S[i]=0.f;

    const size_t hb = ((size_t)b*TQ*HQ + h)*64;
    const float* qg = g_qn + hb;
    const float* kg = g_kn + hb;
    const float* vg = g_vn + hb + half*32;
    const float* bg = g_beta  + (size_t)b*TQ*HQ + h;
    const float* dg = g_decay + (size_t)b*TQ*HQ + h;
    const float* kg2= g_qk    + (size_t)b*TQ*HQ + h;
    float* og = g_osc + hb + half*32 + el;
    const size_t tstr = (size_t)HQ*64;

    const int tt  = tid>>4, d4  = (tid&15)*4;
    const int tv  = tid>>3, dv4 = (tid&7)*4;

    {
        *(float4*)&qs[0][tt*64+d4] = *(const float4*)(qg + (size_t)tt*tstr + d4);
        *(float4*)&ks[0][tt*64+d4] = *(const float4*)(kg + (size_t)tt*tstr + d4);
        if (tid<128)      *(float4*)&vs[0][tv*32+dv4] = *(const float4*)(vg + (size_t)tv*tstr + dv4);
        else if (tid<144) bs[0][tid-128]  = bg [(size_t)(tid-128)*HQ];
        else if (tid<160) ds[0][tid-144]  = dg [(size_t)(tid-144)*HQ];
        else if (tid<176) qks[0][tid-160] = kg2[(size_t)(tid-160)*HQ];
    }
    __syncthreads();

    const int NC = TQ/SCH;
    for (int c=0; c<NC; c++){
        const int cur = c&1, nxt = cur^1;
        float4 pq, pk, pv; float pb=0.f, pd=0.f, pqk=0.f;
        const bool has = (c+1<NC);
        const int t0n = (c+1)*SCH;
        if (has){
            pq = *(const float4*)(qg + (size_t)(t0n+tt)*tstr + d4);
            pk = *(const float4*)(kg + (size_t)(t0n+tt)*tstr + d4);
            if (tid<128)      pv  = *(const float4*)(vg + (size_t)(t0n+tv)*tstr + dv4);
            else if (tid<144) pb  = bg [(size_t)(t0n+tid-128)*HQ];
            else if (tid<160) pd  = dg [(size_t)(t0n+tid-144)*HQ];
            else if (tid<176) pqk = kg2[(size_t)(t0n+tid-160)*HQ];
        }
        const int t0 = c*SCH;
        #pragma unroll 4
        for (int j=0;j<SCH;j++){
            float kr[8], qr[8];
            *(float4*)&kr[0] = *(const float4*)&ks[cur][j*64+d0];
            *(float4*)&kr[4] = *(const float4*)&ks[cur][j*64+d0+4];
            *(float4*)&qr[0] = *(const float4*)&qs[cur][j*64+d0];
            *(float4*)&qr[4] = *(const float4*)&qs[cur][j*64+d0+4];
            float dcy = ds[cur][j];
            float bet = bs[cur][j];
            float vv  = vs[cur][j*32+el];
            float qk  = qks[cur][j];
            // both reductions on S_old (parallel)
            float p0=0.f,p1=0.f,o0=0.f,o1=0.f;
            #pragma unroll
            for (int i=0;i<8;i+=2){
                p0 += kr[i]  *S[i];   o0 += qr[i]  *S[i];
                p1 += kr[i+1]*S[i+1]; o1 += qr[i+1]*S[i+1];
            }
            float pred = p0+p1;
            pred += __shfl_xor_sync(0xffffffffu, pred, 1);
            pred += __shfl_xor_sync(0xffffffffu, pred, 2);
            pred += __shfl_xor_sync(0xffffffffu, pred, 4);
            float be = bet*(vv - dcy*pred);
            #pragma unroll
            for (int i=0;i<8;i++)
                S[i] = fmaf(dcy, S[i], be*kr[i]);
            // o-reduction off the serial chain
            float oq = o0+o1;
            oq += __shfl_xor_sync(0xffffffffu, oq, 1);
            oq += __shfl_xor_sync(0xffffffffu, oq, 2);
            oq += __shfl_xor_sync(0xffffffffu, oq, 4);
            float oo = fmaf(dcy, oq, qk*be);
            if (s==0) og[(size_t)(t0+j)*tstr] = oo;
        }
        __syncthreads();
        if (has){
            *(float4*)&qs[nxt][tt*64+d4] = pq;
            *(float4*)&ks[nxt][tt*64+d4] = pk;
            if (tid<128)      *(float4*)&vs[nxt][tv*32+dv4] = pv;
            else if (tid<144) bs[nxt][tid-128]  = pb;
            else if (tid<160) ds[nxt][tid-144]  = pd;
            else if (tid<176) qks[nxt][tid-160] = pqk;
        }
        __syncthreads();
    }
}

// ---------------- output gate: rmsnorm(o,64)*o_norm_scale * silu(gate) ----------------
__global__ __launch_bounds__(256) void gate_kernel(const float* __restrict__ onorm)
{
    int row = blockIdx.x;
    int tid = threadIdx.x;
    int c0 = tid*4;
    size_t off = (size_t)row*DQ + c0;
    float4 o = *(const float4*)(g_osc + off);
    float ss = o.x*o.x+o.y*o.y+o.z*o.z+o.w*o.w;
    ss += __shfl_xor_sync(0xffffffffu, ss, 1);
    ss += __shfl_xor_sync(0xffffffffu, ss, 2);
    ss += __shfl_xor_sync(0xffffffffu, ss, 4);
    ss += __shfl_xor_sync(0xffffffffu, ss, 8);
    float denom = rsqrtf(ss*(1.0f/64.f) + 1e-5f);
    int dv = c0 & 63;
    float4 w = *(const float4*)(onorm + dv);
    float4 g = *(const float4*)(g_pre + (size_t)row*NW + 3072 + c0);
    float4 res;
    res.x = o.x*denom*w.x*siluf(g.x);
    res.y = o.y*denom*w.y*siluf(g.y);
    res.z = o.z*denom*w.z*siluf(g.z);
    res.w = o.w*denom*w.w*siluf(g.w);
    *(float4*)(g_gated + off) = res;
}

// ---------------- launch ----------------
extern "C" void kernel_launch(void* const* d_in, const int* in_sizes, int n_in,
                              void* d_out, int out_size)
{
    const float* x      = (const float*)d_in[0];
    const float* nscale = (const float*)d_in[1];
    const float* wq     = (const float*)d_in[2];
    const float* wk     = (const float*)d_in[3];
    const float* wv     = (const float*)d_in[4];
    const float* qcw    = (const float*)d_in[5];
    const float* kcw    = (const float*)d_in[6];
    const float* vcw    = (const float*)d_in[7];
    const float* aproj  = (const float*)d_in[8];
    const float* Alog   = (const float*)d_in[9];
    const float* dtb    = (const float*)d_in[10];
    const float* bproj  = (const float*)d_in[11];
    const float* gproj  = (const float*)d_in[12];
    const float* onorm  = (const float*)d_in[13];
    const float* wo     = (const float*)d_in[14];
    float* out = (float*)d_out;

    void *pxn, *pwbig, *ppre, *pgated;
    cudaGetSymbolAddress(&pxn,   g_xn);
    cudaGetSymbolAddress(&pwbig, g_wbig);
    cudaGetSymbolAddress(&ppre,  g_pre);
    cudaGetSymbolAddress(&pgated,g_gated);

    rmsnorm_kernel<<<ROWS, 256>>>(x, nscale);
    concat_w<<<DQ, 256>>>(wq, wk, wv, gproj, bproj, aproj);

    dim3 gbig(NW/128, ROWS/128);   // (33, 64)
    gemm_fp16<<<gbig, 256>>>((const float*)pxn, (const float*)pwbig, nullptr,
                             (float*)ppre, NW, 0);

    conv_kernel<<<ROWS, 256>>>(qcw, kcw, vcw);
    betadecay_kernel<<<ROWS*32/256, 256>>>(Alog, dtb);

    scan_kernel<<<BQ*HQ*2, 256>>>();

    gate_kernel<<<ROWS, 256>>>(onorm);

    dim3 gwo(DQ/128, ROWS/128);    // (8, 64)
    gemm_fp16<<<gwo, 256>>>((const float*)pgated, wo, x, out, DQ, 1);
}

// round 6
// speedup vs baseline: 2.3320x; 1.1780x over previous
#include <cuda_runtime.h>
#include <cuda_fp16.h>
#include <cstdint>

// Problem constants
#define BQ   4
#define TQ   2048
#define DQ   1024
#define HQ   16
#define ROWS (BQ*TQ)   // 8192
#define NW   4224      // fused projection width: q|k|v|g|bp|ap|pad

// ---------------- scratch (static device memory) ----------------
__device__ __half g_xnh  [ROWS*DQ];
__device__ __half g_wbh  [(size_t)DQ*NW];
__device__ __half g_woh  [DQ*DQ];
__device__ __half g_gatedh[ROWS*DQ];
__device__ float g_pre  [(size_t)ROWS*NW];
__device__ float g_qn   [ROWS*DQ];
__device__ float g_kn   [ROWS*DQ];
__device__ float g_vn   [ROWS*DQ];
__device__ float g_beta [ROWS*HQ];
__device__ float g_decay[ROWS*HQ];
__device__ float g_qk   [ROWS*HQ];
__device__ float g_osc  [ROWS*DQ];

__device__ __forceinline__ float siluf(float x){ return x/(1.0f+expf(-x)); }
__device__ __forceinline__ uint32_t smem_u32(const void* p){
    uint32_t a;
    asm("{ .reg .u64 t; cvta.to.shared.u64 t, %1; cvt.u32.u64 %0, t; }" : "=r"(a) : "l"(p));
    return a;
}
__device__ __forceinline__ void store_h4(__half* dst, float a, float b, float c, float d){
    __half2 h0 = __floats2half2_rn(a, b);
    __half2 h1 = __floats2half2_rn(c, d);
    uint2 u;
    u.x = *reinterpret_cast<uint32_t*>(&h0);
    u.y = *reinterpret_cast<uint32_t*>(&h1);
    *(uint2*)dst = u;
}

// ---------------- RMSNorm over D=1024 (fp16 out) ----------------
__global__ __launch_bounds__(256) void rmsnorm_kernel(const float* __restrict__ x,
                                                      const float* __restrict__ w)
{
    int row = blockIdx.x;
    const float* xr = x + (size_t)row*DQ;
    int tid = threadIdx.x;
    float4 v = *(const float4*)(xr + tid*4);
    float ss = v.x*v.x+v.y*v.y+v.z*v.z+v.w*v.w;
    #pragma unroll
    for (int m=16;m>0;m>>=1) ss += __shfl_xor_sync(0xffffffffu, ss, m);
    __shared__ float sred[8];
    if ((tid&31)==0) sred[tid>>5]=ss;
    __syncthreads();
    if (tid<8){
        float t = sred[tid];
        #pragma unroll
        for (int m=4;m>0;m>>=1) t += __shfl_xor_sync(0xffu, t, m);
        if (tid==0) sred[0]=t;
    }
    __syncthreads();
    float denom = rsqrtf(sred[0]*(1.0f/DQ) + 1e-5f);
    float4 wv = *(const float4*)(w + tid*4);
    store_h4(g_xnh + (size_t)row*DQ + tid*4,
             v.x*denom*wv.x, v.y*denom*wv.y, v.z*denom*wv.z, v.w*denom*wv.w);
}

// ---------------- weight concat (fp16): Wbig[K=1024][4224] ----------------
__global__ __launch_bounds__(256) void concat_w(const float* __restrict__ wq,
                                                const float* __restrict__ wk,
                                                const float* __restrict__ wv,
                                                const float* __restrict__ gp,
                                                const float* __restrict__ bp,
                                                const float* __restrict__ ap)
{
    int k = blockIdx.x;     // 0..1023
    __half* o = g_wbh + (size_t)k*NW;
    for (int c4 = threadIdx.x; c4 < NW/4; c4 += 256){
        int c = c4*4;
        float4 v;
        if      (c < 1024) v = *(const float4*)(wq + (size_t)k*DQ + c);
        else if (c < 2048) v = *(const float4*)(wk + (size_t)k*DQ + c - 1024);
        else if (c < 3072) v = *(const float4*)(wv + (size_t)k*DQ + c - 2048);
        else if (c < 4096) v = *(const float4*)(gp + (size_t)k*DQ + c - 3072);
        else if (c < 4112) v = *(const float4*)(bp + (size_t)k*HQ + c - 4096);
        else if (c < 4128) v = *(const float4*)(ap + (size_t)k*HQ + c - 4112);
        else               v = make_float4(0.f,0.f,0.f,0.f);
        store_h4(o + c, v.x, v.y, v.z, v.w);
    }
}

// ---------------- wo -> fp16 ----------------
__global__ __launch_bounds__(256) void conv_wo(const float* __restrict__ wo)
{
    int i = blockIdx.x*256 + threadIdx.x;   // DQ*DQ/4
    float4 v = *(const float4*)(wo + (size_t)i*4);
    store_h4(g_woh + (size_t)i*4, v.x, v.y, v.z, v.w);
}

// ---------------- fp16 GEMM: C[M,Nw]=A[M,1024]@W[1024,Nw] (+Res), cp.async+ldmatrix ----------------
#define KTG 32
#define NKT (DQ/KTG)      // 32
#define STAGES 3
#define A_STRIDE 80       // bytes per A smem row (64B data + 16B pad)
#define B_STRIDE 272      // bytes per B smem row (256B data + 16B pad)
#define A_BYTES (128*A_STRIDE)          // 10240
#define B_BYTES (KTG*B_STRIDE)          // 8704
#define STAGE_BYTES (A_BYTES + B_BYTES) // 18944
#define GEMM_SMEM (STAGES*STAGE_BYTES)  // 56832

__global__ __launch_bounds__(256,2) void gemm_fp16(const __half* __restrict__ A,
                                                   const __half* __restrict__ W,
                                                   const float* __restrict__ Res,
                                                   float* __restrict__ C,
                                                   int Nw, int residual)
{
    extern __shared__ char smem[];
    const uint32_t sbase = smem_u32(smem);
    const int tid = threadIdx.x;
    const int wid = tid>>5, lane = tid&31;
    const int bm = blockIdx.y*128, bn = blockIdx.x*128;
    const int wm = (wid>>2)*64, wn = (wid&3)*32;
    const int r = lane>>2, c4 = lane&3;

    float acc[4][4][4];
    #pragma unroll
    for (int i=0;i<4;i++)
        #pragma unroll
        for (int j=0;j<4;j++)
            #pragma unroll
            for (int k=0;k<4;k++) acc[i][j][k]=0.f;

    auto issue_stage = [&](int s, int k0){
        uint32_t sa = sbase + s*STAGE_BYTES;
        uint32_t sb = sa + A_BYTES;
        #pragma unroll
        for (int i=0;i<2;i++){
            int c = tid + i*256;
            int ar = c>>2, ac = c&3;
            const __half* asrc = A + (size_t)(bm+ar)*DQ + k0 + ac*8;
            uint32_t adst = sa + ar*A_STRIDE + ac*16;
            asm volatile("cp.async.cg.shared.global [%0], [%1], 16;" :: "r"(adst), "l"(asrc) : "memory");
            int br = c>>4, bc = c&15;
            const __half* bsrc = W + (size_t)(k0+br)*Nw + bn + bc*8;
            uint32_t bdst = sb + br*B_STRIDE + bc*16;
            asm volatile("cp.async.cg.shared.global [%0], [%1], 16;" :: "r"(bdst), "l"(bsrc) : "memory");
        }
    };
    auto compute_stage = [&](int s){
        uint32_t sa = sbase + s*STAGE_BYTES;
        uint32_t sb = sa + A_BYTES;
        uint32_t aaddr0 = sa + (uint32_t)(wm + (lane&15))*A_STRIDE + (lane>>4)*16;
        uint32_t baddr0 = sb + (uint32_t)(lane&15)*B_STRIDE + wn*2 + (lane>>4)*16;
        #pragma unroll
        for (int ks=0; ks<2; ks++){
            uint32_t af[4][4];
            #pragma unroll
            for (int mt=0;mt<4;mt++){
                uint32_t ad = aaddr0 + mt*16*A_STRIDE + ks*32;
                asm volatile("ldmatrix.sync.aligned.m8n8.x4.shared.b16 {%0,%1,%2,%3}, [%4];"
                  : "=r"(af[mt][0]),"=r"(af[mt][1]),"=r"(af[mt][2]),"=r"(af[mt][3]) : "r"(ad));
            }
            uint32_t bf[2][4];
            #pragma unroll
            for (int ntp=0;ntp<2;ntp++){
                uint32_t bd = baddr0 + ks*16*B_STRIDE + ntp*32;
                asm volatile("ldmatrix.sync.aligned.m8n8.x4.trans.shared.b16 {%0,%1,%2,%3}, [%4];"
                  : "=r"(bf[ntp][0]),"=r"(bf[ntp][1]),"=r"(bf[ntp][2]),"=r"(bf[ntp][3]) : "r"(bd));
            }
            #pragma unroll
            for (int mt=0;mt<4;mt++)
                #pragma unroll
                for (int nt=0;nt<4;nt++){
                    uint32_t b0 = bf[nt>>1][(nt&1)*2], b1 = bf[nt>>1][(nt&1)*2+1];
                    asm volatile(
                      "mma.sync.aligned.m16n8k16.row.col.f32.f16.f16.f32 "
                      "{%0,%1,%2,%3},{%4,%5,%6,%7},{%8,%9},{%0,%1,%2,%3};"
                      : "+f"(acc[mt][nt][0]),"+f"(acc[mt][nt][1]),
                        "+f"(acc[mt][nt][2]),"+f"(acc[mt][nt][3])
                      : "r"(af[mt][0]),"r"(af[mt][1]),"r"(af[mt][2]),"r"(af[mt][3]),
                        "r"(b0),"r"(b1));
                }
        }
    };

    issue_stage(0, 0);
    asm volatile("cp.async.commit_group;" ::: "memory");
    issue_stage(1, KTG);
    asm volatile("cp.async.commit_group;" ::: "memory");

    for (int it=0; it<NKT; it++){
        asm volatile("cp.async.wait_group 1;" ::: "memory");
        __syncthreads();
        compute_stage(it % STAGES);
        if (it+2 < NKT) issue_stage((it+2) % STAGES, (it+2)*KTG);
        asm volatile("cp.async.commit_group;" ::: "memory");
    }

    #pragma unroll
    for (int mt=0;mt<4;mt++){
        #pragma unroll
        for (int nt=0;nt<4;nt++){
            int m0 = bm + wm + mt*16 + r;
            int n0 = bn + wn + nt*8 + c4*2;
            size_t i0 = (size_t)m0*Nw + n0;
            size_t i1 = (size_t)(m0+8)*Nw + n0;
            float2 v0 = make_float2(acc[mt][nt][0], acc[mt][nt][1]);
            float2 v1 = make_float2(acc[mt][nt][2], acc[mt][nt][3]);
            if (residual){
                float2 r0 = *(const float2*)(Res + i0);
                float2 r1 = *(const float2*)(Res + i1);
                v0.x+=r0.x; v0.y+=r0.y; v1.x+=r1.x; v1.y+=r1.y;
            }
            *(float2*)(C+i0)=v0;
            *(float2*)(C+i1)=v1;
        }
    }
}

// ---------------- depthwise causal conv (K=4) + SiLU + L2 norm + qk dot ----------------
__device__ __forceinline__ void conv4(const float* __restrict__ base,
                                      const float* __restrict__ w, int c0, int t,
                                      float& a0, float& a1, float& a2, float& a3)
{
    float4 w0 = *(const float4*)(w + (size_t)(c0+0)*4);
    float4 w1 = *(const float4*)(w + (size_t)(c0+1)*4);
    float4 w2 = *(const float4*)(w + (size_t)(c0+2)*4);
    float4 w3 = *(const float4*)(w + (size_t)(c0+3)*4);
    a0=0.f; a1=0.f; a2=0.f; a3=0.f;
    #pragma unroll
    for (int j=0;j<4;j++){
        if (t-j >= 0){
            float4 xv = *(const float4*)(base - (size_t)j*NW);
            a0 += xv.x*((const float*)&w0)[j];
            a1 += xv.y*((const float*)&w1)[j];
            a2 += xv.z*((const float*)&w2)[j];
            a3 += xv.w*((const float*)&w3)[j];
        }
    }
    a0 = siluf(a0); a1 = siluf(a1); a2 = siluf(a2); a3 = siluf(a3);
}

__device__ __forceinline__ void l2n4(float& a0, float& a1, float& a2, float& a3, float scale)
{
    float ss = a0*a0+a1*a1+a2*a2+a3*a3;
    ss += __shfl_xor_sync(0xffffffffu, ss, 1);
    ss += __shfl_xor_sync(0xffffffffu, ss, 2);
    ss += __shfl_xor_sync(0xffffffffu, ss, 4);
    ss += __shfl_xor_sync(0xffffffffu, ss, 8);
    float inv = scale / fmaxf(sqrtf(ss), 1e-12f);
    a0*=inv; a1*=inv; a2*=inv; a3*=inv;
}

__global__ __launch_bounds__(256) void conv_kernel(const float* __restrict__ qw,
                                                   const float* __restrict__ kw,
                                                   const float* __restrict__ vw)
{
    int bt = blockIdx.x;
    int t  = bt & (TQ-1);
    int tid = threadIdx.x;
    int c0 = tid*4;
    const float* rowbase = g_pre + (size_t)bt*NW + c0;
    size_t off = (size_t)bt*DQ + c0;

    float q0,q1,q2,q3, k0,k1,k2,k3, v0,v1,v2,v3;
    conv4(rowbase,          qw, c0, t, q0,q1,q2,q3);
    l2n4(q0,q1,q2,q3, 0.125f);
    *(float4*)(g_qn + off) = make_float4(q0,q1,q2,q3);

    conv4(rowbase + 1024,   kw, c0, t, k0,k1,k2,k3);
    l2n4(k0,k1,k2,k3, 1.0f);
    *(float4*)(g_kn + off) = make_float4(k0,k1,k2,k3);

    float qk = q0*k0 + q1*k1 + q2*k2 + q3*k3;
    qk += __shfl_xor_sync(0xffffffffu, qk, 1);
    qk += __shfl_xor_sync(0xffffffffu, qk, 2);
    qk += __shfl_xor_sync(0xffffffffu, qk, 4);
    qk += __shfl_xor_sync(0xffffffffu, qk, 8);
    if ((tid & 15) == 0) g_qk[(size_t)bt*HQ + (tid>>4)] = qk;

    conv4(rowbase + 2048,   vw, c0, t, v0,v1,v2,v3);
    *(float4*)(g_vn + off) = make_float4(v0,v1,v2,v3);
}

// ---------------- beta / decay from fused GEMM columns ----------------
__global__ __launch_bounds__(256) void betadecay_kernel(const float* __restrict__ Alog,
                                                        const float* __restrict__ dtb)
{
    int i = blockIdx.x*256 + threadIdx.x;   // ROWS*32
    int row = i >> 5, c = i & 31;
    float s = g_pre[(size_t)row*NW + 4096 + c];
    if (c < HQ){
        g_beta[(size_t)row*HQ + c] = 1.0f/(1.0f+expf(-s));
    } else {
        int h = c - HQ;
        float xdt = s + dtb[h];
        float sp = (xdt>20.f) ? xdt : log1pf(expf(xdt));
        g_decay[(size_t)row*HQ + h] = expf(-expf(Alog[h])*sp);
    }
}

// ---------------- gated delta-rule scan (shortened critical path) ----------------
#define SCH 16
__global__ __launch_bounds__(256) void scan_kernel()
{
    const int half = blockIdx.x & 1;
    const int bh   = blockIdx.x >> 1;
    const int b = bh >> 4, h = bh & 15;
    const int tid = threadIdx.x;
    const int el = tid >> 3;       // DV column within half: 0..31
    const int s  = tid & 7;        // DK split: 0..7
    const int d0 = s*8;

    __shared__ float qs[2][SCH*64];
    __shared__ float ks[2][SCH*64];
    __shared__ float vs[2][SCH*32];
    __shared__ float bs[2][SCH];
    __shared__ float ds[2][SCH];
    __shared__ float qks[2][SCH];

    float S[8];
    #pragma unroll
    for (int i=0;i<8;i++) S[i]=0.f;

    const size_t hb = ((size_t)b*TQ*HQ + h)*64;
    const float* qg = g_qn + hb;
    const float* kg = g_kn + hb;
    const float* vg = g_vn + hb + half*32;
    const float* bg = g_beta  + (size_t)b*TQ*HQ + h;
    const float* dg = g_decay + (size_t)b*TQ*HQ + h;
    const float* kg2= g_qk    + (size_t)b*TQ*HQ + h;
    float* og = g_osc + hb + half*32 + el;
    const size_t tstr = (size_t)HQ*64;

    const int tt  = tid>>4, d4  = (tid&15)*4;
    const int tv  = tid>>3, dv4 = (tid&7)*4;

    {
        *(float4*)&qs[0][tt*64+d4] = *(const float4*)(qg + (size_t)tt*tstr + d4);
        *(float4*)&ks[0][tt*64+d4] = *(const float4*)(kg + (size_t)tt*tstr + d4);
        if (tid<128)      *(float4*)&vs[0][tv*32+dv4] = *(const float4*)(vg + (size_t)tv*tstr + dv4);
        else if (tid<144) bs[0][tid-128]  = bg [(size_t)(tid-128)*HQ];
        else if (tid<160) ds[0][tid-144]  = dg [(size_t)(tid-144)*HQ];
        else if (tid<176) qks[0][tid-160] = kg2[(size_t)(tid-160)*HQ];
    }
    __syncthreads();

    const int NC = TQ/SCH;
    for (int c=0; c<NC; c++){
        const int cur = c&1, nxt = cur^1;
        float4 pq, pk, pv; float pb=0.f, pd=0.f, pqk=0.f;
        const bool has = (c+1<NC);
        const int t0n = (c+1)*SCH;
        if (has){
            pq = *(const float4*)(qg + (size_t)(t0n+tt)*tstr + d4);
            pk = *(const float4*)(kg + (size_t)(t0n+tt)*tstr + d4);
            if (tid<128)      pv  = *(const float4*)(vg + (size_t)(t0n+tv)*tstr + dv4);
            else if (tid<144) pb  = bg [(size_t)(t0n+tid-128)*HQ];
            else if (tid<160) pd  = dg [(size_t)(t0n+tid-144)*HQ];
            else if (tid<176) pqk = kg2[(size_t)(t0n+tid-160)*HQ];
        }
        const int t0 = c*SCH;
        #pragma unroll 4
        for (int j=0;j<SCH;j++){
            float kr[8], qr[8];
            *(float4*)&kr[0] = *(const float4*)&ks[cur][j*64+d0];
            *(float4*)&kr[4] = *(const float4*)&ks[cur][j*64+d0+4];
            *(float4*)&qr[0] = *(const float4*)&qs[cur][j*64+d0];
            *(float4*)&qr[4] = *(const float4*)&qs[cur][j*64+d0+4];
            float dcy = ds[cur][j];
            float bet = bs[cur][j];
            float vv  = vs[cur][j*32+el];
            float qk  = qks[cur][j];
            float p0=0.f,p1=0.f,o0=0.f,o1=0.f;
            #pragma unroll
            for (int i=0;i<8;i+=2){
                p0 += kr[i]  *S[i];   o0 += qr[i]  *S[i];
                p1 += kr[i+1]*S[i+1]; o1 += qr[i+1]*S[i+1];
            }
            float pred = p0+p1;
            pred += __shfl_xor_sync(0xffffffffu, pred, 1);
            pred += __shfl_xor_sync(0xffffffffu, pred, 2);
            pred += __shfl_xor_sync(0xffffffffu, pred, 4);
            float be = bet*(vv - dcy*pred);
            #pragma unroll
            for (int i=0;i<8;i++)
                S[i] = fmaf(dcy, S[i], be*kr[i]);
            float oq = o0+o1;
            oq += __shfl_xor_sync(0xffffffffu, oq, 1);
            oq += __shfl_xor_sync(0xffffffffu, oq, 2);
            oq += __shfl_xor_sync(0xffffffffu, oq, 4);
            float oo = fmaf(dcy, oq, qk*be);
            if (s==0) og[(size_t)(t0+j)*tstr] = oo;
        }
        __syncthreads();
        if (has){
            *(float4*)&qs[nxt][tt*64+d4] = pq;
            *(float4*)&ks[nxt][tt*64+d4] = pk;
            if (tid<128)      *(float4*)&vs[nxt][tv*32+dv4] = pv;
            else if (tid<144) bs[nxt][tid-128]  = pb;
            else if (tid<160) ds[nxt][tid-144]  = pd;
            else if (tid<176) qks[nxt][tid-160] = pqk;
        }
        __syncthreads();
    }
}

// ---------------- output gate: rmsnorm(o,64)*o_norm_scale * silu(gate) (fp16 out) ----------------
__global__ __launch_bounds__(256) void gate_kernel(const float* __restrict__ onorm)
{
    int row = blockIdx.x;
    int tid = threadIdx.x;
    int c0 = tid*4;
    size_t off = (size_t)row*DQ + c0;
    float4 o = *(const float4*)(g_osc + off);
    float ss = o.x*o.x+o.y*o.y+o.z*o.z+o.w*o.w;
    ss += __shfl_xor_sync(0xffffffffu, ss, 1);
    ss += __shfl_xor_sync(0xffffffffu, ss, 2);
    ss += __shfl_xor_sync(0xffffffffu, ss, 4);
    ss += __shfl_xor_sync(0xffffffffu, ss, 8);
    float denom = rsqrtf(ss*(1.0f/64.f) + 1e-5f);
    int dv = c0 & 63;
    float4 w = *(const float4*)(onorm + dv);
    float4 g = *(const float4*)(g_pre + (size_t)row*NW + 3072 + c0);
    store_h4(g_gatedh + off,
             o.x*denom*w.x*siluf(g.x),
             o.y*denom*w.y*siluf(g.y),
             o.z*denom*w.z*siluf(g.z),
             o.w*denom*w.w*siluf(g.w));
}

// ---------------- launch ----------------
extern "C" void kernel_launch(void* const* d_in, const int* in_sizes, int n_in,
                              void* d_out, int out_size)
{
    const float* x      = (const float*)d_in[0];
    const float* nscale = (const float*)d_in[1];
    const float* wq     = (const float*)d_in[2];
    const float* wk     = (const float*)d_in[3];
    const float* wv     = (const float*)d_in[4];
    const float* qcw    = (const float*)d_in[5];
    const float* kcw    = (const float*)d_in[6];
    const float* vcw    = (const float*)d_in[7];
    const float* aproj  = (const float*)d_in[8];
    const float* Alog   = (const float*)d_in[9];
    const float* dtb    = (const float*)d_in[10];
    const float* bproj  = (const float*)d_in[11];
    const float* gproj  = (const float*)d_in[12];
    const float* onorm  = (const float*)d_in[13];
    const float* wo     = (const float*)d_in[14];
    float* out = (float*)d_out;

    void *pxnh, *pwbh, *pwoh, *ppre, *pgatedh;
    cudaGetSymbolAddress(&pxnh,   g_xnh);
    cudaGetSymbolAddress(&pwbh,   g_wbh);
    cudaGetSymbolAddress(&pwoh,   g_woh);
    cudaGetSymbolAddress(&ppre,   g_pre);
    cudaGetSymbolAddress(&pgatedh,g_gatedh);

    cudaFuncSetAttribute(gemm_fp16, cudaFuncAttributeMaxDynamicSharedMemorySize, GEMM_SMEM);

    rmsnorm_kernel<<<ROWS, 256>>>(x, nscale);
    concat_w<<<DQ, 256>>>(wq, wk, wv, gproj, bproj, aproj);
    conv_wo<<<DQ*DQ/1024, 256>>>(wo);

    dim3 gbig(NW/128, ROWS/128);   // (33, 64)
    gemm_fp16<<<gbig, 256, GEMM_SMEM>>>((const __half*)pxnh, (const __half*)pwbh, nullptr,
                                        (float*)ppre, NW, 0);

    conv_kernel<<<ROWS, 256>>>(qcw, kcw, vcw);
    betadecay_kernel<<<ROWS*32/256, 256>>>(Alog, dtb);

    scan_kernel<<<BQ*HQ*2, 256>>>();

    gate_kernel<<<ROWS, 256>>>(onorm);

    dim3 gwo(DQ/128, ROWS/128);    // (8, 64)
    gemm_fp16<<<gwo, 256, GEMM_SMEM>>>((const __half*)pgatedh, (const __half*)pwoh, x, out, DQ, 1);
}

// round 7
// speedup vs baseline: 2.4458x; 1.0488x over previous
#include <cuda_runtime.h>
#include <cuda_fp16.h>
#include <cstdint>

// Problem constants
#define BQ   4
#define TQ   2048
#define DQ   1024
#define HQ   16
#define ROWS (BQ*TQ)   // 8192
#define NW   4224      // fused projection width: q|k|v|g|bp|ap|pad

// ---------------- scratch (static device memory) ----------------
__device__ __half g_xnh  [ROWS*DQ];
__device__ __half g_wbh  [(size_t)DQ*NW];
__device__ __half g_woh  [DQ*DQ];
__device__ __half g_gatedh[ROWS*DQ];
__device__ float g_pre  [(size_t)ROWS*NW];
__device__ float g_qn   [ROWS*DQ];
__device__ float g_kn   [ROWS*DQ];
__device__ float g_vn   [ROWS*DQ];
__device__ float g_beta [ROWS*HQ];
__device__ float g_decay[ROWS*HQ];
__device__ float g_qk   [ROWS*HQ];
__device__ float g_osc  [ROWS*DQ];

__device__ __forceinline__ float siluf(float x){ return x/(1.0f+expf(-x)); }
__device__ __forceinline__ uint32_t smem_u32(const void* p){
    uint32_t a;
    asm("{ .reg .u64 t; cvta.to.shared.u64 t, %1; cvt.u32.u64 %0, t; }" : "=r"(a) : "l"(p));
    return a;
}
__device__ __forceinline__ void store_h4(__half* dst, float a, float b, float c, float d){
    __half2 h0 = __floats2half2_rn(a, b);
    __half2 h1 = __floats2half2_rn(c, d);
    uint2 u;
    u.x = *reinterpret_cast<uint32_t*>(&h0);
    u.y = *reinterpret_cast<uint32_t*>(&h1);
    *(uint2*)dst = u;
}

// ---------------- RMSNorm over D=1024 (fp16 out) ----------------
__global__ __launch_bounds__(256) void rmsnorm_kernel(const float* __restrict__ x,
                                                      const float* __restrict__ w)
{
    int row = blockIdx.x;
    const float* xr = x + (size_t)row*DQ;
    int tid = threadIdx.x;
    float4 v = *(const float4*)(xr + tid*4);
    float ss = v.x*v.x+v.y*v.y+v.z*v.z+v.w*v.w;
    #pragma unroll
    for (int m=16;m>0;m>>=1) ss += __shfl_xor_sync(0xffffffffu, ss, m);
    __shared__ float sred[8];
    if ((tid&31)==0) sred[tid>>5]=ss;
    __syncthreads();
    if (tid<8){
        float t = sred[tid];
        #pragma unroll
        for (int m=4;m>0;m>>=1) t += __shfl_xor_sync(0xffu, t, m);
        if (tid==0) sred[0]=t;
    }
    __syncthreads();
    float denom = rsqrtf(sred[0]*(1.0f/DQ) + 1e-5f);
    float4 wv = *(const float4*)(w + tid*4);
    store_h4(g_xnh + (size_t)row*DQ + tid*4,
             v.x*denom*wv.x, v.y*denom*wv.y, v.z*denom*wv.z, v.w*denom*wv.w);
}

// ---------------- weight concat (fp16): Wbig[K=1024][4224] ----------------
__global__ __launch_bounds__(256) void concat_w(const float* __restrict__ wq,
                                                const float* __restrict__ wk,
                                                const float* __restrict__ wv,
                                                const float* __restrict__ gp,
                                                const float* __restrict__ bp,
                                                const float* __restrict__ ap)
{
    int k = blockIdx.x;     // 0..1023
    __half* o = g_wbh + (size_t)k*NW;
    for (int c4 = threadIdx.x; c4 < NW/4; c4 += 256){
        int c = c4*4;
        float4 v;
        if      (c < 1024) v = *(const float4*)(wq + (size_t)k*DQ + c);
        else if (c < 2048) v = *(const float4*)(wk + (size_t)k*DQ + c - 1024);
        else if (c < 3072) v = *(const float4*)(wv + (size_t)k*DQ + c - 2048);
        else if (c < 4096) v = *(const float4*)(gp + (size_t)k*DQ + c - 3072);
        else if (c < 4112) v = *(const float4*)(bp + (size_t)k*HQ + c - 4096);
        else if (c < 4128) v = *(const float4*)(ap + (size_t)k*HQ + c - 4112);
        else               v = make_float4(0.f,0.f,0.f,0.f);
        store_h4(o + c, v.x, v.y, v.z, v.w);
    }
}

// ---------------- wo -> fp16 ----------------
__global__ __launch_bounds__(256) void conv_wo(const float* __restrict__ wo)
{
    int i = blockIdx.x*256 + threadIdx.x;   // DQ*DQ/4
    float4 v = *(const float4*)(wo + (size_t)i*4);
    store_h4(g_woh + (size_t)i*4, v.x, v.y, v.z, v.w);
}

// ---------------- fp16 GEMM: C[M,Nw]=A[M,1024]@W[1024,Nw] (+Res), cp.async+ldmatrix ----------------
#define KTG 32
#define NKT (DQ/KTG)      // 32
#define STAGES 3
#define A_STRIDE 80       // bytes per A smem row (64B data + 16B pad)
#define B_STRIDE 272      // bytes per B smem row (256B data + 16B pad)
#define A_BYTES (128*A_STRIDE)          // 10240
#define B_BYTES (KTG*B_STRIDE)          // 8704
#define STAGE_BYTES (A_BYTES + B_BYTES) // 18944
#define GEMM_SMEM (STAGES*STAGE_BYTES)  // 56832

__global__ __launch_bounds__(256,2) void gemm_fp16(const __half* __restrict__ A,
                                                   const __half* __restrict__ W,
                                                   const float* __restrict__ Res,
                                                   float* __restrict__ C,
                                                   int Nw, int residual)
{
    extern __shared__ char smem[];
    const uint32_t sbase = smem_u32(smem);
    const int tid = threadIdx.x;
    const int wid = tid>>5, lane = tid&31;
    const int bm = blockIdx.y*128, bn = blockIdx.x*128;
    const int wm = (wid>>2)*64, wn = (wid&3)*32;
    const int r = lane>>2, c4 = lane&3;

    float acc[4][4][4];
    #pragma unroll
    for (int i=0;i<4;i++)
        #pragma unroll
        for (int j=0;j<4;j++)
            #pragma unroll
            for (int k=0;k<4;k++) acc[i][j][k]=0.f;

    auto issue_stage = [&](int s, int k0){
        uint32_t sa = sbase + s*STAGE_BYTES;
        uint32_t sb = sa + A_BYTES;
        #pragma unroll
        for (int i=0;i<2;i++){
            int c = tid + i*256;
            int ar = c>>2, ac = c&3;
            const __half* asrc = A + (size_t)(bm+ar)*DQ + k0 + ac*8;
            uint32_t adst = sa + ar*A_STRIDE + ac*16;
            asm volatile("cp.async.cg.shared.global [%0], [%1], 16;" :: "r"(adst), "l"(asrc) : "memory");
            int br = c>>4, bc = c&15;
            const __half* bsrc = W + (size_t)(k0+br)*Nw + bn + bc*8;
            uint32_t bdst = sb + br*B_STRIDE + bc*16;
            asm volatile("cp.async.cg.shared.global [%0], [%1], 16;" :: "r"(bdst), "l"(bsrc) : "memory");
        }
    };
    auto compute_stage = [&](int s){
        uint32_t sa = sbase + s*STAGE_BYTES;
        uint32_t sb = sa + A_BYTES;
        uint32_t aaddr0 = sa + (uint32_t)(wm + (lane&15))*A_STRIDE + (lane>>4)*16;
        uint32_t baddr0 = sb + (uint32_t)(lane&15)*B_STRIDE + wn*2 + (lane>>4)*16;
        #pragma unroll
        for (int ks=0; ks<2; ks++){
            uint32_t af[4][4];
            #pragma unroll
            for (int mt=0;mt<4;mt++){
                uint32_t ad = aaddr0 + mt*16*A_STRIDE + ks*32;
                asm volatile("ldmatrix.sync.aligned.m8n8.x4.shared.b16 {%0,%1,%2,%3}, [%4];"
                  : "=r"(af[mt][0]),"=r"(af[mt][1]),"=r"(af[mt][2]),"=r"(af[mt][3]) : "r"(ad));
            }
            uint32_t bf[2][4];
            #pragma unroll
            for (int ntp=0;ntp<2;ntp++){
                uint32_t bd = baddr0 + ks*16*B_STRIDE + ntp*32;
                asm volatile("ldmatrix.sync.aligned.m8n8.x4.trans.shared.b16 {%0,%1,%2,%3}, [%4];"
                  : "=r"(bf[ntp][0]),"=r"(bf[ntp][1]),"=r"(bf[ntp][2]),"=r"(bf[ntp][3]) : "r"(bd));
            }
            #pragma unroll
            for (int mt=0;mt<4;mt++)
                #pragma unroll
                for (int nt=0;nt<4;nt++){
                    uint32_t b0 = bf[nt>>1][(nt&1)*2], b1 = bf[nt>>1][(nt&1)*2+1];
                    asm volatile(
                      "mma.sync.aligned.m16n8k16.row.col.f32.f16.f16.f32 "
                      "{%0,%1,%2,%3},{%4,%5,%6,%7},{%8,%9},{%0,%1,%2,%3};"
                      : "+f"(acc[mt][nt][0]),"+f"(acc[mt][nt][1]),
                        "+f"(acc[mt][nt][2]),"+f"(acc[mt][nt][3])
                      : "r"(af[mt][0]),"r"(af[mt][1]),"r"(af[mt][2]),"r"(af[mt][3]),
                        "r"(b0),"r"(b1));
                }
        }
    };

    issue_stage(0, 0);
    asm volatile("cp.async.commit_group;" ::: "memory");
    issue_stage(1, KTG);
    asm volatile("cp.async.commit_group;" ::: "memory");

    for (int it=0; it<NKT; it++){
        asm volatile("cp.async.wait_group 1;" ::: "memory");
        __syncthreads();
        compute_stage(it % STAGES);
        if (it+2 < NKT) issue_stage((it+2) % STAGES, (it+2)*KTG);
        asm volatile("cp.async.commit_group;" ::: "memory");
    }

    #pragma unroll
    for (int mt=0;mt<4;mt++){
        #pragma unroll
        for (int nt=0;nt<4;nt++){
            int m0 = bm + wm + mt*16 + r;
            int n0 = bn + wn + nt*8 + c4*2;
            size_t i0 = (size_t)m0*Nw + n0;
            size_t i1 = (size_t)(m0+8)*Nw + n0;
            float2 v0 = make_float2(acc[mt][nt][0], acc[mt][nt][1]);
            float2 v1 = make_float2(acc[mt][nt][2], acc[mt][nt][3]);
            if (residual){
                float2 r0 = *(const float2*)(Res + i0);
                float2 r1 = *(const float2*)(Res + i1);
                v0.x+=r0.x; v0.y+=r0.y; v1.x+=r1.x; v1.y+=r1.y;
            }
            *(float2*)(C+i0)=v0;
            *(float2*)(C+i1)=v1;
        }
    }
}

// ---------------- depthwise causal conv (K=4) + SiLU + L2 norm + qk dot ----------------
__device__ __forceinline__ void conv4(const float* __restrict__ base,
                                      const float* __restrict__ w, int c0, int t,
                                      float& a0, float& a1, float& a2, float& a3)
{
    float4 w0 = *(const float4*)(w + (size_t)(c0+0)*4);
    float4 w1 = *(const float4*)(w + (size_t)(c0+1)*4);
    float4 w2 = *(const float4*)(w + (size_t)(c0+2)*4);
    float4 w3 = *(const float4*)(w + (size_t)(c0+3)*4);
    a0=0.f; a1=0.f; a2=0.f; a3=0.f;
    #pragma unroll
    for (int j=0;j<4;j++){
        if (t-j >= 0){
            float4 xv = *(const float4*)(base - (size_t)j*NW);
            a0 += xv.x*((const float*)&w0)[j];
            a1 += xv.y*((const float*)&w1)[j];
            a2 += xv.z*((const float*)&w2)[j];
            a3 += xv.w*((const float*)&w3)[j];
        }
    }
    a0 = siluf(a0); a1 = siluf(a1); a2 = siluf(a2); a3 = siluf(a3);
}

__device__ __forceinline__ void l2n4(float& a0, float& a1, float& a2, float& a3, float scale)
{
    float ss = a0*a0+a1*a1+a2*a2+a3*a3;
    ss += __shfl_xor_sync(0xffffffffu, ss, 1);
    ss += __shfl_xor_sync(0xffffffffu, ss, 2);
    ss += __shfl_xor_sync(0xffffffffu, ss, 4);
    ss += __shfl_xor_sync(0xffffffffu, ss, 8);
    float inv = scale / fmaxf(sqrtf(ss), 1e-12f);
    a0*=inv; a1*=inv; a2*=inv; a3*=inv;
}

__global__ __launch_bounds__(256) void conv_kernel(const float* __restrict__ qw,
                                                   const float* __restrict__ kw,
                                                   const float* __restrict__ vw)
{
    int bt = blockIdx.x;
    int t  = bt & (TQ-1);
    int tid = threadIdx.x;
    int c0 = tid*4;
    const float* rowbase = g_pre + (size_t)bt*NW + c0;
    size_t off = (size_t)bt*DQ + c0;

    float q0,q1,q2,q3, k0,k1,k2,k3, v0,v1,v2,v3;
    conv4(rowbase,          qw, c0, t, q0,q1,q2,q3);
    l2n4(q0,q1,q2,q3, 0.125f);
    *(float4*)(g_qn + off) = make_float4(q0,q1,q2,q3);

    conv4(rowbase + 1024,   kw, c0, t, k0,k1,k2,k3);
    l2n4(k0,k1,k2,k3, 1.0f);
    *(float4*)(g_kn + off) = make_float4(k0,k1,k2,k3);

    float qk = q0*k0 + q1*k1 + q2*k2 + q3*k3;
    qk += __shfl_xor_sync(0xffffffffu, qk, 1);
    qk += __shfl_xor_sync(0xffffffffu, qk, 2);
    qk += __shfl_xor_sync(0xffffffffu, qk, 4);
    qk += __shfl_xor_sync(0xffffffffu, qk, 8);
    if ((tid & 15) == 0) g_qk[(size_t)bt*HQ + (tid>>4)] = qk;

    conv4(rowbase + 2048,   vw, c0, t, v0,v1,v2,v3);
    *(float4*)(g_vn + off) = make_float4(v0,v1,v2,v3);
}

// ---------------- beta / decay from fused GEMM columns ----------------
__global__ __launch_bounds__(256) void betadecay_kernel(const float* __restrict__ Alog,
                                                        const float* __restrict__ dtb)
{
    int i = blockIdx.x*256 + threadIdx.x;   // ROWS*32
    int row = i >> 5, c = i & 31;
    float s = g_pre[(size_t)row*NW + 4096 + c];
    if (c < HQ){
        g_beta[(size_t)row*HQ + c] = 1.0f/(1.0f+expf(-s));
    } else {
        int h = c - HQ;
        float xdt = s + dtb[h];
        float sp = (xdt>20.f) ? xdt : log1pf(expf(xdt));
        g_decay[(size_t)row*HQ + h] = expf(-expf(Alog[h])*sp);
    }
}

// ---------------- gated delta-rule scan: 128 thr/CTA, DK-split 4, cp.async chunks ----------------
#define SCCH 32
__global__ __launch_bounds__(128) void scan_kernel()
{
    const int half = blockIdx.x & 1;
    const int bh   = blockIdx.x >> 1;
    const int b = bh >> 4, h = bh & 15;
    const int tid = threadIdx.x;
    const int s  = tid & 3;        // DK split: 0..3
    const int el = tid >> 2;       // DV column within half: 0..31
    const int d0 = s*16;

    __shared__ float ks[2][SCCH][64];
    __shared__ float qs[2][SCCH][64];
    __shared__ float vs[2][SCCH][32];
    __shared__ float sb[2][SCCH];
    __shared__ float sd[2][SCCH];
    __shared__ float sq[2][SCCH];

    float S[16];
    #pragma unroll
    for (int i=0;i<16;i++) S[i]=0.f;

    const size_t hb = ((size_t)b*TQ*HQ + h)*64;
    const float* kg = g_kn + hb;
    const float* qg = g_qn + hb;
    const float* vg = g_vn + hb + half*32;
    const float* bg = g_beta  + (size_t)b*TQ*HQ + h;
    const float* dg = g_decay + (size_t)b*TQ*HQ + h;
    const float* qkg= g_qk    + (size_t)b*TQ*HQ + h;
    float* og = g_osc + hb + half*32 + el;

    auto issue_chunk = [&](int buf, int c0){
        #pragma unroll
        for (int p=0;p<4;p++){
            int i = tid + p*128;
            int t = i>>4, g4 = (i&15)*4;
            uint32_t kd = smem_u32(&ks[buf][t][g4]);
            uint32_t qd = smem_u32(&qs[buf][t][g4]);
            const float* ksrc = kg + (size_t)(c0+t)*DQ + g4;
            const float* qsrc = qg + (size_t)(c0+t)*DQ + g4;
            asm volatile("cp.async.cg.shared.global [%0], [%1], 16;" :: "r"(kd), "l"(ksrc) : "memory");
            asm volatile("cp.async.cg.shared.global [%0], [%1], 16;" :: "r"(qd), "l"(qsrc) : "memory");
        }
        #pragma unroll
        for (int p=0;p<2;p++){
            int i = tid + p*128;
            int t = i>>3, g4 = (i&7)*4;
            uint32_t vd = smem_u32(&vs[buf][t][g4]);
            const float* vsrc = vg + (size_t)(c0+t)*DQ + g4;
            asm volatile("cp.async.cg.shared.global [%0], [%1], 16;" :: "r"(vd), "l"(vsrc) : "memory");
        }
        if (tid < 96){
            int t = tid & 31;
            int which = tid >> 5;     // 0:beta 1:decay 2:qk
            const float* src = (which==0 ? bg : (which==1 ? dg : qkg)) + (size_t)(c0+t)*HQ;
            uint32_t dd = smem_u32(which==0 ? &sb[buf][t] : (which==1 ? &sd[buf][t] : &sq[buf][t]));
            asm volatile("cp.async.ca.shared.global [%0], [%1], 4;" :: "r"(dd), "l"(src) : "memory");
        }
        asm volatile("cp.async.commit_group;" ::: "memory");
    };

    issue_chunk(0, 0);
    const int NC = TQ/SCCH;   // 64
    for (int c=0; c<NC; c++){
        asm volatile("cp.async.wait_group 0;" ::: "memory");
        __syncthreads();
        if (c+1 < NC) issue_chunk((c+1)&1, (c+1)*SCCH);
        const int buf = c&1;
        const int t0 = c*SCCH;
        #pragma unroll 2
        for (int j=0;j<SCCH;j++){
            float kr[16], qr[16];
            #pragma unroll
            for (int i=0;i<16;i+=4){
                *(float4*)&kr[i] = *(const float4*)&ks[buf][j][d0+i];
                *(float4*)&qr[i] = *(const float4*)&qs[buf][j][d0+i];
            }
            float dcy = sd[buf][j];
            float bet = sb[buf][j];
            float qk  = sq[buf][j];
            float vv  = vs[buf][j][el];
            float p0=0.f,p1=0.f,o0=0.f,o1=0.f;
            #pragma unroll
            for (int i=0;i<16;i+=2){
                p0 = fmaf(kr[i],  S[i],  p0);  o0 = fmaf(qr[i],  S[i],  o0);
                p1 = fmaf(kr[i+1],S[i+1],p1);  o1 = fmaf(qr[i+1],S[i+1],o1);
            }
            float p = p0+p1, oq = o0+o1;
            p  += __shfl_xor_sync(0xffffffffu, p, 1);
            p  += __shfl_xor_sync(0xffffffffu, p, 2);
            oq += __shfl_xor_sync(0xffffffffu, oq, 1);
            oq += __shfl_xor_sync(0xffffffffu, oq, 2);
            float be = bet * fmaf(-dcy, p, vv);
            #pragma unroll
            for (int i=0;i<16;i++)
                S[i] = fmaf(be, kr[i], dcy*S[i]);
            if (s==0) og[(size_t)(t0+j)*DQ] = fmaf(dcy, oq, qk*be);
        }
    }
}

// ---------------- output gate: rmsnorm(o,64)*o_norm_scale * silu(gate) (fp16 out) ----------------
__global__ __launch_bounds__(256) void gate_kernel(const float* __restrict__ onorm)
{
    int row = blockIdx.x;
    int tid = threadIdx.x;
    int c0 = tid*4;
    size_t off = (size_t)row*DQ + c0;
    float4 o = *(const float4*)(g_osc + off);
    float ss = o.x*o.x+o.y*o.y+o.z*o.z+o.w*o.w;
    ss += __shfl_xor_sync(0xffffffffu, ss, 1);
    ss += __shfl_xor_sync(0xffffffffu, ss, 2);
    ss += __shfl_xor_sync(0xffffffffu, ss, 4);
    ss += __shfl_xor_sync(0xffffffffu, ss, 8);
    float denom = rsqrtf(ss*(1.0f/64.f) + 1e-5f);
    int dv = c0 & 63;
    float4 w = *(const float4*)(onorm + dv);
    float4 g = *(const float4*)(g_pre + (size_t)row*NW + 3072 + c0);
    store_h4(g_gatedh + off,
             o.x*denom*w.x*siluf(g.x),
             o.y*denom*w.y*siluf(g.y),
             o.z*denom*w.z*siluf(g.z),
             o.w*denom*w.w*siluf(g.w));
}

// ---------------- launch ----------------
extern "C" void kernel_launch(void* const* d_in, const int* in_sizes, int n_in,
                              void* d_out, int out_size)
{
    const float* x      = (const float*)d_in[0];
    const float* nscale = (const float*)d_in[1];
    const float* wq     = (const float*)d_in[2];
    const float* wk     = (const float*)d_in[3];
    const float* wv     = (const float*)d_in[4];
    const float* qcw    = (const float*)d_in[5];
    const float* kcw    = (const float*)d_in[6];
    const float* vcw    = (const float*)d_in[7];
    const float* aproj  = (const float*)d_in[8];
    const float* Alog   = (const float*)d_in[9];
    const float* dtb    = (const float*)d_in[10];
    const float* bproj  = (const float*)d_in[11];
    const float* gproj  = (const float*)d_in[12];
    const float* onorm  = (const float*)d_in[13];
    const float* wo     = (const float*)d_in[14];
    float* out = (float*)d_out;

    void *pxnh, *pwbh, *pwoh, *ppre, *pgatedh;
    cudaGetSymbolAddress(&pxnh,   g_xnh);
    cudaGetSymbolAddress(&pwbh,   g_wbh);
    cudaGetSymbolAddress(&pwoh,   g_woh);
    cudaGetSymbolAddress(&ppre,   g_pre);
    cudaGetSymbolAddress(&pgatedh,g_gatedh);

    cudaFuncSetAttribute(gemm_fp16, cudaFuncAttributeMaxDynamicSharedMemorySize, GEMM_SMEM);

    rmsnorm_kernel<<<ROWS, 256>>>(x, nscale);
    concat_w<<<DQ, 256>>>(wq, wk, wv, gproj, bproj, aproj);
    conv_wo<<<DQ*DQ/1024, 256>>>(wo);

    dim3 gbig(NW/128, ROWS/128);   // (33, 64)
    gemm_fp16<<<gbig, 256, GEMM_SMEM>>>((const __half*)pxnh, (const __half*)pwbh, nullptr,
                                        (float*)ppre, NW, 0);

    conv_kernel<<<ROWS, 256>>>(qcw, kcw, vcw);
    betadecay_kernel<<<ROWS*32/256, 256>>>(Alog, dtb);

    scan_kernel<<<BQ*HQ*2, 128>>>();

    gate_kernel<<<ROWS, 256>>>(onorm);

    dim3 gwo(DQ/128, ROWS/128);    // (8, 64)
    gemm_fp16<<<gwo, 256, GEMM_SMEM>>>((const __half*)pgatedh, (const __half*)pwoh, x, out, DQ, 1);
}